// round 1
// baseline (speedup 1.0000x reference)
#include <cuda_runtime.h>

#define SEQ  2048
#define DM   1024
#define NH   16
#define HDIM 64
#define FFD  4096

// ---------------- scratch (no allocations allowed) ----------------
__device__ float g_Q[NH * SEQ * HDIM];            // 8 MB
__device__ float g_K[NH * SEQ * HDIM];            // 8 MB
__device__ float g_V[NH * SEQ * HDIM];            // 8 MB
__device__ float g_attn[(size_t)NH * SEQ * SEQ];  // 256 MB
__device__ float g_concat[SEQ * DM];              // 8 MB
__device__ float g_proj[SEQ * DM];                // 8 MB
__device__ float g_hidden[SEQ * FFD];             // 32 MB

// =====================================================================
// Generic 128x128x16 SGEMM: C = A(MxK) @ B(KxN) + bias[n], optional ReLU
// 256 threads, 8x8 micro-tile per thread. M,N,K multiples of 128/16.
// =====================================================================
template <int RELU>
__global__ __launch_bounds__(256)
void sgemm_nn(const float* __restrict__ A, const float* __restrict__ B,
              const float* __restrict__ bias, float* __restrict__ C,
              int M, int N, int K)
{
    __shared__ float As[16][128];
    __shared__ float Bs[16][128];

    const int tid = threadIdx.x;
    const int tx  = tid & 15;        // 0..15 -> 8 cols each
    const int ty  = tid >> 4;        // 0..15 -> 8 rows each
    const int bm  = blockIdx.y * 128;
    const int bn  = blockIdx.x * 128;

    const int arow = tid >> 2;             // 0..63
    const int acol = (tid & 3) << 2;       // 0,4,8,12
    const int brow = tid >> 5;             // 0..7
    const int bcol = (tid & 31) << 2;      // 0..124

    float acc[8][8];
    #pragma unroll
    for (int i = 0; i < 8; i++)
        #pragma unroll
        for (int j = 0; j < 8; j++) acc[i][j] = 0.f;

    for (int k0 = 0; k0 < K; k0 += 16) {
        float4 a0 = *(const float4*)(A + (size_t)(bm + arow)      * K + k0 + acol);
        float4 a1 = *(const float4*)(A + (size_t)(bm + arow + 64) * K + k0 + acol);
        As[acol + 0][arow] = a0.x; As[acol + 1][arow] = a0.y;
        As[acol + 2][arow] = a0.z; As[acol + 3][arow] = a0.w;
        As[acol + 0][arow + 64] = a1.x; As[acol + 1][arow + 64] = a1.y;
        As[acol + 2][arow + 64] = a1.z; As[acol + 3][arow + 64] = a1.w;

        float4 b0 = *(const float4*)(B + (size_t)(k0 + brow)     * N + bn + bcol);
        float4 b1 = *(const float4*)(B + (size_t)(k0 + brow + 8) * N + bn + bcol);
        *(float4*)&Bs[brow][bcol]     = b0;
        *(float4*)&Bs[brow + 8][bcol] = b1;

        __syncthreads();
        #pragma unroll
        for (int kk = 0; kk < 16; kk++) {
            float ar[8], br[8];
            *(float4*)&ar[0] = *(const float4*)&As[kk][ty * 8];
            *(float4*)&ar[4] = *(const float4*)&As[kk][ty * 8 + 4];
            *(float4*)&br[0] = *(const float4*)&Bs[kk][tx * 8];
            *(float4*)&br[4] = *(const float4*)&Bs[kk][tx * 8 + 4];
            #pragma unroll
            for (int i = 0; i < 8; i++)
                #pragma unroll
                for (int j = 0; j < 8; j++)
                    acc[i][j] = fmaf(ar[i], br[j], acc[i][j]);
        }
        __syncthreads();
    }

    #pragma unroll
    for (int i = 0; i < 8; i++) {
        const int row = bm + ty * 8 + i;
        #pragma unroll
        for (int j = 0; j < 8; j += 4) {
            const int col = bn + tx * 8 + j;
            float4 bb = *(const float4*)(bias + col);
            float4 v;
            v.x = acc[i][j + 0] + bb.x;
            v.y = acc[i][j + 1] + bb.y;
            v.z = acc[i][j + 2] + bb.z;
            v.w = acc[i][j + 3] + bb.w;
            if (RELU) {
                v.x = fmaxf(v.x, 0.f); v.y = fmaxf(v.y, 0.f);
                v.z = fmaxf(v.z, 0.f); v.w = fmaxf(v.w, 0.f);
            }
            *(float4*)(C + (size_t)row * N + col) = v;
        }
    }
}

// =====================================================================
// QKV projection: Out[h,s,e] = sum_d X[s,d] * W[h,d,e] + bias[h*64+e]
// Same tiling as sgemm_nn; B and C addressing remapped per-head.
// M=SEQ, N=DM (=NH*HDIM), K=DM.
// =====================================================================
__global__ __launch_bounds__(256)
void sgemm_qkv(const float* __restrict__ X, const float* __restrict__ W,
               const float* __restrict__ bias, float* __restrict__ Out)
{
    __shared__ float As[16][128];
    __shared__ float Bs[16][128];

    const int tid = threadIdx.x;
    const int tx  = tid & 15;
    const int ty  = tid >> 4;
    const int bm  = blockIdx.y * 128;
    const int bn  = blockIdx.x * 128;

    const int arow = tid >> 2;
    const int acol = (tid & 3) << 2;
    const int brow = tid >> 5;
    const int bcol = (tid & 31) << 2;

    float acc[8][8];
    #pragma unroll
    for (int i = 0; i < 8; i++)
        #pragma unroll
        for (int j = 0; j < 8; j++) acc[i][j] = 0.f;

    // W element (k, n): W[(n>>6)*DM*HDIM + k*HDIM + (n&63)]
    const int nb   = bn + bcol;
    const int head = nb >> 6;
    const int noff = nb & 63;
    const float* Wb = W + (size_t)head * DM * HDIM + noff;

    for (int k0 = 0; k0 < DM; k0 += 16) {
        float4 a0 = *(const float4*)(X + (size_t)(bm + arow)      * DM + k0 + acol);
        float4 a1 = *(const float4*)(X + (size_t)(bm + arow + 64) * DM + k0 + acol);
        As[acol + 0][arow] = a0.x; As[acol + 1][arow] = a0.y;
        As[acol + 2][arow] = a0.z; As[acol + 3][arow] = a0.w;
        As[acol + 0][arow + 64] = a1.x; As[acol + 1][arow + 64] = a1.y;
        As[acol + 2][arow + 64] = a1.z; As[acol + 3][arow + 64] = a1.w;

        float4 b0 = *(const float4*)(Wb + (size_t)(k0 + brow)     * HDIM);
        float4 b1 = *(const float4*)(Wb + (size_t)(k0 + brow + 8) * HDIM);
        *(float4*)&Bs[brow][bcol]     = b0;
        *(float4*)&Bs[brow + 8][bcol] = b1;

        __syncthreads();
        #pragma unroll
        for (int kk = 0; kk < 16; kk++) {
            float ar[8], br[8];
            *(float4*)&ar[0] = *(const float4*)&As[kk][ty * 8];
            *(float4*)&ar[4] = *(const float4*)&As[kk][ty * 8 + 4];
            *(float4*)&br[0] = *(const float4*)&Bs[kk][tx * 8];
            *(float4*)&br[4] = *(const float4*)&Bs[kk][tx * 8 + 4];
            #pragma unroll
            for (int i = 0; i < 8; i++)
                #pragma unroll
                for (int j = 0; j < 8; j++)
                    acc[i][j] = fmaf(ar[i], br[j], acc[i][j]);
        }
        __syncthreads();
    }

    #pragma unroll
    for (int i = 0; i < 8; i++) {
        const int row = bm + ty * 8 + i;
        #pragma unroll
        for (int j = 0; j < 8; j += 4) {
            const int col = bn + tx * 8 + j;     // global feature index
            const int h   = col >> 6;
            const int e   = col & 63;
            float4 bb = *(const float4*)(bias + col);
            float4 v;
            v.x = acc[i][j + 0] + bb.x;
            v.y = acc[i][j + 1] + bb.y;
            v.z = acc[i][j + 2] + bb.z;
            v.w = acc[i][j + 3] + bb.w;
            *(float4*)(Out + (size_t)h * SEQ * HDIM + (size_t)row * HDIM + e) = v;
        }
    }
}

// =====================================================================
// scores[h,s,t] = (Q[h,s,:] . K[h,t,:]) / 8   (NT GEMM, K=64)
// =====================================================================
__global__ __launch_bounds__(256)
void scores_kernel(const float* __restrict__ gQ, const float* __restrict__ gKm,
                   float* __restrict__ gAttn)
{
    const int h = blockIdx.z;
    const float* Aq = gQ  + (size_t)h * SEQ * HDIM;
    const float* Bk = gKm + (size_t)h * SEQ * HDIM;
    float* Cc       = gAttn + (size_t)h * SEQ * SEQ;

    __shared__ float As[16][128];
    __shared__ float Bs[16][128];

    const int tid = threadIdx.x;
    const int tx  = tid & 15;
    const int ty  = tid >> 4;
    const int bm  = blockIdx.y * 128;
    const int bn  = blockIdx.x * 128;

    const int arow = tid >> 2;           // 0..63
    const int acol = (tid & 3) << 2;     // 0..12

    float acc[8][8];
    #pragma unroll
    for (int i = 0; i < 8; i++)
        #pragma unroll
        for (int j = 0; j < 8; j++) acc[i][j] = 0.f;

    for (int k0 = 0; k0 < HDIM; k0 += 16) {
        float4 a0 = *(const float4*)(Aq + (size_t)(bm + arow)      * HDIM + k0 + acol);
        float4 a1 = *(const float4*)(Aq + (size_t)(bm + arow + 64) * HDIM + k0 + acol);
        As[acol + 0][arow] = a0.x; As[acol + 1][arow] = a0.y;
        As[acol + 2][arow] = a0.z; As[acol + 3][arow] = a0.w;
        As[acol + 0][arow + 64] = a1.x; As[acol + 1][arow + 64] = a1.y;
        As[acol + 2][arow + 64] = a1.z; As[acol + 3][arow + 64] = a1.w;

        // B is K-matrix rows (t), NT: Bs[k][t]
        float4 b0 = *(const float4*)(Bk + (size_t)(bn + arow)      * HDIM + k0 + acol);
        float4 b1 = *(const float4*)(Bk + (size_t)(bn + arow + 64) * HDIM + k0 + acol);
        Bs[acol + 0][arow] = b0.x; Bs[acol + 1][arow] = b0.y;
        Bs[acol + 2][arow] = b0.z; Bs[acol + 3][arow] = b0.w;
        Bs[acol + 0][arow + 64] = b1.x; Bs[acol + 1][arow + 64] = b1.y;
        Bs[acol + 2][arow + 64] = b1.z; Bs[acol + 3][arow + 64] = b1.w;

        __syncthreads();
        #pragma unroll
        for (int kk = 0; kk < 16; kk++) {
            float ar[8], br[8];
            *(float4*)&ar[0] = *(const float4*)&As[kk][ty * 8];
            *(float4*)&ar[4] = *(const float4*)&As[kk][ty * 8 + 4];
            *(float4*)&br[0] = *(const float4*)&Bs[kk][tx * 8];
            *(float4*)&br[4] = *(const float4*)&Bs[kk][tx * 8 + 4];
            #pragma unroll
            for (int i = 0; i < 8; i++)
                #pragma unroll
                for (int j = 0; j < 8; j++)
                    acc[i][j] = fmaf(ar[i], br[j], acc[i][j]);
        }
        __syncthreads();
    }

    #pragma unroll
    for (int i = 0; i < 8; i++) {
        const int row = bm + ty * 8 + i;
        #pragma unroll
        for (int j = 0; j < 8; j += 4) {
            const int col = bn + tx * 8 + j;
            float4 v;
            v.x = acc[i][j + 0] * 0.125f;
            v.y = acc[i][j + 1] * 0.125f;
            v.z = acc[i][j + 2] * 0.125f;
            v.w = acc[i][j + 3] * 0.125f;
            *(float4*)(Cc + (size_t)row * SEQ + col) = v;
        }
    }
}

// =====================================================================
// In-place row softmax over t: attn has NH*SEQ rows of length SEQ.
// One block per row, 256 threads, 8 elements/thread kept in registers.
// =====================================================================
__global__ __launch_bounds__(256)
void softmax_kernel(float* __restrict__ attn)
{
    __shared__ float red[8];
    float* p = attn + (size_t)blockIdx.x * SEQ;
    const int t = threadIdx.x;
    const int lane = t & 31, warp = t >> 5;

    float v[8];
    #pragma unroll
    for (int i = 0; i < 8; i++) v[i] = p[t + i * 256];

    float m = v[0];
    #pragma unroll
    for (int i = 1; i < 8; i++) m = fmaxf(m, v[i]);
    #pragma unroll
    for (int o = 16; o > 0; o >>= 1) m = fmaxf(m, __shfl_xor_sync(0xffffffffu, m, o));
    if (lane == 0) red[warp] = m;
    __syncthreads();
    float mm = red[0];
    #pragma unroll
    for (int i = 1; i < 8; i++) mm = fmaxf(mm, red[i]);
    __syncthreads();

    float s = 0.f;
    #pragma unroll
    for (int i = 0; i < 8; i++) { v[i] = __expf(v[i] - mm); s += v[i]; }
    #pragma unroll
    for (int o = 16; o > 0; o >>= 1) s += __shfl_xor_sync(0xffffffffu, s, o);
    if (lane == 0) red[warp] = s;
    __syncthreads();
    float ss = 0.f;
    #pragma unroll
    for (int i = 0; i < 8; i++) ss += red[i];
    const float inv = 1.f / ss;

    #pragma unroll
    for (int i = 0; i < 8; i++) p[t + i * 256] = v[i] * inv;
}

// =====================================================================
// heads/concat: concat[t, h*64+e] = sum_s attn[h,s,t] * V[h,s,e]
// Per (t-block, head): BM=128 (t), BN=64 (e), BK=16 (s). TM=8, TN=4.
// attn tile load is coalesced along t (attn[s*SEQ + t]).
// =====================================================================
__global__ __launch_bounds__(256)
void av_kernel(const float* __restrict__ gAttn, const float* __restrict__ gV,
               float* __restrict__ concat)
{
    const int h  = blockIdx.y;
    const int bt = blockIdx.x * 128;
    const float* Ah = gAttn + (size_t)h * SEQ * SEQ;
    const float* Vh = gV    + (size_t)h * SEQ * HDIM;

    __shared__ float As[16][128];  // [s][t]
    __shared__ float Bs[16][64];   // [s][e]

    const int tid = threadIdx.x;
    const int tx  = tid & 15;      // e: tx*4
    const int ty  = tid >> 4;      // t: ty*8

    const int si  = tid >> 5;             // 0..7
    const int t4  = (tid & 31) << 2;      // 0..124
    const int si2 = tid >> 4;             // 0..15
    const int e4  = (tid & 15) << 2;      // 0..60

    float acc[8][4];
    #pragma unroll
    for (int i = 0; i < 8; i++)
        #pragma unroll
        for (int j = 0; j < 4; j++) acc[i][j] = 0.f;

    for (int k0 = 0; k0 < SEQ; k0 += 16) {
        float4 a0 = *(const float4*)(Ah + (size_t)(k0 + si)     * SEQ + bt + t4);
        float4 a1 = *(const float4*)(Ah + (size_t)(k0 + si + 8) * SEQ + bt + t4);
        *(float4*)&As[si][t4]     = a0;
        *(float4*)&As[si + 8][t4] = a1;

        float4 b = *(const float4*)(Vh + (size_t)(k0 + si2) * HDIM + e4);
        *(float4*)&Bs[si2][e4] = b;

        __syncthreads();
        #pragma unroll
        for (int kk = 0; kk < 16; kk++) {
            float ar[8], br[4];
            *(float4*)&ar[0] = *(const float4*)&As[kk][ty * 8];
            *(float4*)&ar[4] = *(const float4*)&As[kk][ty * 8 + 4];
            *(float4*)&br[0] = *(const float4*)&Bs[kk][tx * 4];
            #pragma unroll
            for (int i = 0; i < 8; i++)
                #pragma unroll
                for (int j = 0; j < 4; j++)
                    acc[i][j] = fmaf(ar[i], br[j], acc[i][j]);
        }
        __syncthreads();
    }

    #pragma unroll
    for (int i = 0; i < 8; i++) {
        const int row = bt + ty * 8 + i;
        float4 v;
        v.x = acc[i][0]; v.y = acc[i][1]; v.z = acc[i][2]; v.w = acc[i][3];
        *(float4*)(concat + (size_t)row * DM + h * HDIM + tx * 4) = v;
    }
}

// =====================================================================
extern "C" void kernel_launch(void* const* d_in, const int* in_sizes, int n_in,
                              void* d_out, int out_size)
{
    const float* x  = (const float*)d_in[0];
    const float* Wq = (const float*)d_in[1];
    const float* bq = (const float*)d_in[2];
    const float* Wk = (const float*)d_in[3];
    const float* bk = (const float*)d_in[4];
    const float* Wv = (const float*)d_in[5];
    const float* bv = (const float*)d_in[6];
    const float* Wp = (const float*)d_in[7];
    const float* bp = (const float*)d_in[8];
    const float* W1 = (const float*)d_in[9];
    const float* b1 = (const float*)d_in[10];
    const float* W2 = (const float*)d_in[11];
    const float* b2 = (const float*)d_in[12];
    float* out = (float*)d_out;

    float *Q, *K, *V, *attn, *concat, *proj, *hidden;
    cudaGetSymbolAddress((void**)&Q,      g_Q);
    cudaGetSymbolAddress((void**)&K,      g_K);
    cudaGetSymbolAddress((void**)&V,      g_V);
    cudaGetSymbolAddress((void**)&attn,   g_attn);
    cudaGetSymbolAddress((void**)&concat, g_concat);
    cudaGetSymbolAddress((void**)&proj,   g_proj);
    cudaGetSymbolAddress((void**)&hidden, g_hidden);

    // 1) QKV projections: [2048,1024] @ per-head [1024,64]x16
    dim3 gProj(DM / 128, SEQ / 128);
    sgemm_qkv<<<gProj, 256>>>(x, Wq, bq, Q);
    sgemm_qkv<<<gProj, 256>>>(x, Wk, bk, K);
    sgemm_qkv<<<gProj, 256>>>(x, Wv, bv, V);

    // 2) scores = Q K^T / 8  (per head)
    scores_kernel<<<dim3(SEQ / 128, SEQ / 128, NH), 256>>>(Q, K, attn);

    // 3) softmax over t (row-wise)
    softmax_kernel<<<NH * SEQ, 256>>>(attn);

    // 4) concat[t, h*64+e] = sum_s attn[h,s,t] V[h,s,e]
    av_kernel<<<dim3(SEQ / 128, NH), 256>>>(attn, V, concat);

    // 5) proj = concat @ Wp + bp
    sgemm_nn<0><<<dim3(DM / 128, SEQ / 128), 256>>>(concat, Wp, bp, proj, SEQ, DM, DM);

    // 6) hidden = relu(proj @ W1 + b1)
    sgemm_nn<1><<<dim3(FFD / 128, SEQ / 128), 256>>>(proj, W1, b1, hidden, SEQ, FFD, DM);

    // 7) out = hidden @ W2 + b2
    sgemm_nn<0><<<dim3(DM / 128, SEQ / 128), 256>>>(hidden, W2, b2, out, SEQ, DM, FFD);
}